// round 16
// baseline (speedup 1.0000x reference)
#include <cuda_runtime.h>
#include <cstdint>

#define NE 64
#define NH 2048
#define NF 1408
#define NM 16

typedef unsigned long long ull;

// SwiGLU intermediate scratch: [E, M, F] fp32 = 5.77 MB
__device__ float g_inter[(size_t)NE * NM * NF];
// down-proj partial sums: [2, E, M, H] fp32 = 16.8 MB
__device__ float g_part[(size_t)2 * NE * NM * NH];

__device__ __forceinline__ ull pack2(float lo, float hi) {
    ull r;
    asm("mov.b64 %0, {%1, %2};" : "=l"(r) : "f"(lo), "f"(hi));
    return r;
}
__device__ __forceinline__ void fma2(ull& d, ull a, ull b) {
    asm("fma.rn.f32x2 %0, %1, %2, %0;" : "+l"(d) : "l"(a), "l"(b));
}
__device__ __forceinline__ float2 unpack2(ull v) {
    float2 r;
    asm("mov.b64 {%0, %1}, %2;" : "=f"(r.x), "=f"(r.y) : "l"(v));
    return r;
}
__device__ __forceinline__ unsigned s2u(const void* p) {
    return (unsigned)__cvta_generic_to_shared(p);
}

#define MBAR_INIT(a, c) \
    asm volatile("mbarrier.init.shared.b64 [%0], %1;" :: "r"(a), "r"(c) : "memory")
#define MBAR_EXPECT(a, tx) \
    asm volatile("mbarrier.arrive.expect_tx.shared.b64 _, [%0], %1;" :: "r"(a), "r"(tx) : "memory")
#define MBAR_ARRIVE(a) \
    asm volatile("mbarrier.arrive.shared.b64 _, [%0];" :: "r"(a) : "memory")
#define MBAR_WAIT(a, ph) do {                                                  \
    unsigned _a = (a), _p = (ph), _d;                                          \
    asm volatile("{\n\t.reg .pred p;\n\t"                                      \
        "mbarrier.try_wait.parity.acquire.cta.shared::cta.b64 p, [%1], %2;\n\t"\
        "selp.b32 %0,1,0,p;\n\t}" : "=r"(_d) : "r"(_a), "r"(_p) : "memory");   \
    if (!_d) {                                                                 \
        asm volatile("{\n\t.reg .pred P1;\n\t"                                 \
            "WL_%=:\n\t"                                                       \
            "mbarrier.try_wait.parity.acquire.cta.shared::cta.b64 P1, [%0], %1, 0x989680;\n\t" \
            "@P1 bra.uni WD_%=;\n\t"                                           \
            "bra.uni WL_%=;\n\t"                                               \
            "WD_%=:\n\t}" :: "r"(_a), "r"(_p) : "memory");                     \
    }                                                                          \
} while (0)

// 1D bulk async copy global->shared, completion via mbarrier complete_tx
#define BULK(dst32, src, nbytes, mbar32) \
    asm volatile("cp.async.bulk.shared::cluster.global.mbarrier::complete_tx::bytes [%0], [%1], %2, [%3];" \
        :: "r"(dst32), "l"(src), "r"(nbytes), "r"(mbar32) : "memory")

#define XS_PAD 20   // 80B row stride, 16B-aligned for LDS.128

// ---------------------------------------------------------------------------
// Kernel 1: inter = silu(x@gate) * (x@up).  64 thr/CTA, 2 f-cols/thread.
// Weights streamed by ONE thread via cp.async.bulk into a 4-stage smem ring
// (stage = 4 h-steps: 4x512B gate + 4x512B up, tx=4096).  grid (11, 64).
// ---------------------------------------------------------------------------
#define K1_CHUNK 256
#define K1_ST_TOT (NH / 4)       // 512 stages
#define K1_ST_CHK (K1_CHUNK / 4) // 64 stages per xs chunk

#define K1_COMP(gv, uv, hrow) do {                                             \
    ull bg0 = pack2((gv).x, (gv).x), bg1 = pack2((gv).y, (gv).y);              \
    ull bu0 = pack2((uv).x, (uv).x), bu1 = pack2((uv).y, (uv).y);              \
    const ulonglong2* xr = reinterpret_cast<const ulonglong2*>(&xs[hrow][0]);  \
    ulonglong2 x01 = xr[0], x23 = xr[1], x45 = xr[2], x67 = xr[3];             \
    fma2(accg[0][0], x01.x, bg0); fma2(accg[1][0], x01.x, bg1);                \
    fma2(accu[0][0], x01.x, bu0); fma2(accu[1][0], x01.x, bu1);                \
    fma2(accg[0][1], x01.y, bg0); fma2(accg[1][1], x01.y, bg1);                \
    fma2(accu[0][1], x01.y, bu0); fma2(accu[1][1], x01.y, bu1);                \
    fma2(accg[0][2], x23.x, bg0); fma2(accg[1][2], x23.x, bg1);                \
    fma2(accu[0][2], x23.x, bu0); fma2(accu[1][2], x23.x, bu1);                \
    fma2(accg[0][3], x23.y, bg0); fma2(accg[1][3], x23.y, bg1);                \
    fma2(accu[0][3], x23.y, bu0); fma2(accu[1][3], x23.y, bu1);                \
    fma2(accg[0][4], x45.x, bg0); fma2(accg[1][4], x45.x, bg1);                \
    fma2(accu[0][4], x45.x, bu0); fma2(accu[1][4], x45.x, bu1);                \
    fma2(accg[0][5], x45.y, bg0); fma2(accg[1][5], x45.y, bg1);                \
    fma2(accu[0][5], x45.y, bu0); fma2(accu[1][5], x45.y, bu1);                \
    fma2(accg[0][6], x67.x, bg0); fma2(accg[1][6], x67.x, bg1);                \
    fma2(accu[0][6], x67.x, bu0); fma2(accu[1][6], x67.x, bu1);                \
    fma2(accg[0][7], x67.y, bg0); fma2(accg[1][7], x67.y, bg1);                \
    fma2(accu[0][7], x67.y, bu0); fma2(accu[1][7], x67.y, bu1);                \
} while (0)

__global__ __launch_bounds__(64) void moe_gateup_kernel(
    const float* __restrict__ x,
    const float* __restrict__ gate,
    const float* __restrict__ up)
{
    __shared__ __align__(16) float xs[K1_CHUNK][XS_PAD];  // 20480 B
    __shared__ __align__(16) float sg[4][4][128];         // 8192 B
    __shared__ __align__(16) float su[4][4][128];         // 8192 B
    __shared__ __align__(8)  ull fullb[4], emptyb[4];

    const int e = blockIdx.y;
    const int tid = threadIdx.x;
    const int f = blockIdx.x * 128 + tid * 2;

    const float* xe = x + (size_t)e * NM * NH;
    const float* gbase = gate + (size_t)e * NH * NF + blockIdx.x * 128;
    const float* ubase = up + (size_t)e * NH * NF + blockIdx.x * 128;

    if (tid == 0) {
#pragma unroll
        for (int s = 0; s < 4; s++) {
            MBAR_INIT(s2u(&fullb[s]), 1);
            MBAR_INIT(s2u(&emptyb[s]), 64);
        }
    }
    __syncthreads();

    ull accg[2][8], accu[2][8];
#pragma unroll
    for (int c = 0; c < 2; c++)
#pragma unroll
        for (int j = 0; j < 8; j++) { accg[c][j] = 0ull; accu[c][j] = 0ull; }

    // prologue: issue stages 0..3
    if (tid == 0) {
#pragma unroll
        for (int tt = 0; tt < 4; tt++) {
            MBAR_EXPECT(s2u(&fullb[tt]), 4096);
#pragma unroll
            for (int r = 0; r < 4; r++) {
                BULK(s2u(&sg[tt][r][0]), gbase + (size_t)(tt * 4 + r) * NF, 512, s2u(&fullb[tt]));
                BULK(s2u(&su[tt][r][0]), ubase + (size_t)(tt * 4 + r) * NF, 512, s2u(&fullb[tt]));
            }
        }
    }

    int t = 0;
    for (int hc = 0; hc < NH; hc += K1_CHUNK) {
        __syncthreads();
#pragma unroll
        for (int mm = 0; mm < NM; mm++) {
#pragma unroll
            for (int hh = tid; hh < K1_CHUNK; hh += 64)
                xs[hh][mm] = xe[(size_t)mm * NH + hc + hh];
        }
        __syncthreads();

        for (int st = 0; st < K1_ST_CHK; st++, t++) {
            const int b = t & 3;
            const unsigned ph = (unsigned)((t >> 2) & 1);
            MBAR_WAIT(s2u(&fullb[b]), ph);
            const int hb = st * 4;
#pragma unroll
            for (int r = 0; r < 4; r++) {
                float2 gv = *reinterpret_cast<const float2*>(&sg[b][r][2 * tid]);
                float2 uv = *reinterpret_cast<const float2*>(&su[b][r][2 * tid]);
                K1_COMP(gv, uv, hb + r);
            }
            MBAR_ARRIVE(s2u(&emptyb[b]));
            if (tid == 0 && t + 4 < K1_ST_TOT) {
                MBAR_WAIT(s2u(&emptyb[b]), ph);
                MBAR_EXPECT(s2u(&fullb[b]), 4096);
                const int tb = t + 4;
#pragma unroll
                for (int r = 0; r < 4; r++) {
                    BULK(s2u(&sg[b][r][0]), gbase + (size_t)(tb * 4 + r) * NF, 512, s2u(&fullb[b]));
                    BULK(s2u(&su[b][r][0]), ubase + (size_t)(tb * 4 + r) * NF, 512, s2u(&fullb[b]));
                }
            }
        }
    }

    float* ip = g_inter + (size_t)e * NM * NF + f;
#pragma unroll
    for (int j = 0; j < 8; j++) {
        float2 g0v = unpack2(accg[0][j]), g1v = unpack2(accg[1][j]);
        float2 u0v = unpack2(accu[0][j]), u1v = unpack2(accu[1][j]);
        float2 o_m0, o_m1;
        o_m0.x = g0v.x / (1.0f + __expf(-g0v.x)) * u0v.x;
        o_m0.y = g1v.x / (1.0f + __expf(-g1v.x)) * u1v.x;
        o_m1.x = g0v.y / (1.0f + __expf(-g0v.y)) * u0v.y;
        o_m1.y = g1v.y / (1.0f + __expf(-g1v.y)) * u1v.y;
        *reinterpret_cast<float2*>(ip + (size_t)(2 * j) * NF)     = o_m0;
        *reinterpret_cast<float2*>(ip + (size_t)(2 * j + 1) * NF) = o_m1;
    }
}

// ---------------------------------------------------------------------------
// Kernel 2: partial down-proj.  64 thr/CTA, 4 h-cols/thread, F-split 2.
// Weight ring: 4 stages x 4 f-steps x 1KB rows (tx=4096).  grid (8, 64, 2).
// ---------------------------------------------------------------------------
#define K2_CHUNK 352
#define K2_FSPLIT 704
#define K2_ST_TOT (K2_FSPLIT / 4)  // 176 stages
#define K2_ST_CHK (K2_CHUNK / 4)   // 88 stages per xs chunk

#define K2_COMP(wv, hrow) do {                                                 \
    ull b0 = pack2((wv).x, (wv).x), b1w = pack2((wv).y, (wv).y);               \
    ull b2w = pack2((wv).z, (wv).z), b3 = pack2((wv).w, (wv).w);               \
    const ulonglong2* xr = reinterpret_cast<const ulonglong2*>(&xs[hrow][0]);  \
    ulonglong2 x01 = xr[0], x23 = xr[1], x45 = xr[2], x67 = xr[3];             \
    fma2(acc[0][0], x01.x, b0);  fma2(acc[1][0], x01.x, b1w);                  \
    fma2(acc[2][0], x01.x, b2w); fma2(acc[3][0], x01.x, b3);                   \
    fma2(acc[0][1], x01.y, b0);  fma2(acc[1][1], x01.y, b1w);                  \
    fma2(acc[2][1], x01.y, b2w); fma2(acc[3][1], x01.y, b3);                   \
    fma2(acc[0][2], x23.x, b0);  fma2(acc[1][2], x23.x, b1w);                  \
    fma2(acc[2][2], x23.x, b2w); fma2(acc[3][2], x23.x, b3);                   \
    fma2(acc[0][3], x23.y, b0);  fma2(acc[1][3], x23.y, b1w);                  \
    fma2(acc[2][3], x23.y, b2w); fma2(acc[3][3], x23.y, b3);                   \
    fma2(acc[0][4], x45.x, b0);  fma2(acc[1][4], x45.x, b1w);                  \
    fma2(acc[2][4], x45.x, b2w); fma2(acc[3][4], x45.x, b3);                   \
    fma2(acc[0][5], x45.y, b0);  fma2(acc[1][5], x45.y, b1w);                  \
    fma2(acc[2][5], x45.y, b2w); fma2(acc[3][5], x45.y, b3);                   \
    fma2(acc[0][6], x67.x, b0);  fma2(acc[1][6], x67.x, b1w);                  \
    fma2(acc[2][6], x67.x, b2w); fma2(acc[3][6], x67.x, b3);                   \
    fma2(acc[0][7], x67.y, b0);  fma2(acc[1][7], x67.y, b1w);                  \
    fma2(acc[2][7], x67.y, b2w); fma2(acc[3][7], x67.y, b3);                   \
} while (0)

__global__ __launch_bounds__(64) void moe_down_kernel(
    const float* __restrict__ down)
{
    __shared__ __align__(16) float xs[K2_CHUNK][XS_PAD];  // 28160 B
    __shared__ __align__(16) float sw[4][4][256];         // 16384 B
    __shared__ __align__(8)  ull fullb[4], emptyb[4];

    const int e = blockIdx.y;
    const int z = blockIdx.z;
    const int tid = threadIdx.x;
    const int h0 = blockIdx.x * 256 + tid * 4;

    const float* ie = g_inter + (size_t)e * NM * NF + (size_t)z * K2_FSPLIT;
    const float* dbase = down + (size_t)e * NF * NH + (size_t)z * K2_FSPLIT * NH + blockIdx.x * 256;

    if (tid == 0) {
#pragma unroll
        for (int s = 0; s < 4; s++) {
            MBAR_INIT(s2u(&fullb[s]), 1);
            MBAR_INIT(s2u(&emptyb[s]), 64);
        }
    }
    __syncthreads();

    ull acc[4][8];
#pragma unroll
    for (int c = 0; c < 4; c++)
#pragma unroll
        for (int j = 0; j < 8; j++) acc[c][j] = 0ull;

    if (tid == 0) {
#pragma unroll
        for (int tt = 0; tt < 4; tt++) {
            MBAR_EXPECT(s2u(&fullb[tt]), 4096);
#pragma unroll
            for (int r = 0; r < 4; r++)
                BULK(s2u(&sw[tt][r][0]), dbase + (size_t)(tt * 4 + r) * NH, 1024, s2u(&fullb[tt]));
        }
    }

    int t = 0;
    for (int fc = 0; fc < K2_FSPLIT; fc += K2_CHUNK) {
        __syncthreads();
#pragma unroll
        for (int mm = 0; mm < NM; mm++) {
            for (int hh = tid; hh < K2_CHUNK; hh += 64)
                xs[hh][mm] = ie[(size_t)mm * NF + fc + hh];
        }
        __syncthreads();

        for (int st = 0; st < K2_ST_CHK; st++, t++) {
            const int b = t & 3;
            const unsigned ph = (unsigned)((t >> 2) & 1);
            MBAR_WAIT(s2u(&fullb[b]), ph);
            const int hb = st * 4;
#pragma unroll
            for (int r = 0; r < 4; r++) {
                float4 wv = *reinterpret_cast<const float4*>(&sw[b][r][4 * tid]);
                K2_COMP(wv, hb + r);
            }
            MBAR_ARRIVE(s2u(&emptyb[b]));
            if (tid == 0 && t + 4 < K2_ST_TOT) {
                MBAR_WAIT(s2u(&emptyb[b]), ph);
                MBAR_EXPECT(s2u(&fullb[b]), 4096);
                const int tb = t + 4;
#pragma unroll
                for (int r = 0; r < 4; r++)
                    BULK(s2u(&sw[b][r][0]), dbase + (size_t)(tb * 4 + r) * NH, 1024, s2u(&fullb[b]));
            }
        }
    }

    float* pp = g_part + ((size_t)z * NE * NM + (size_t)e * NM) * NH + h0;
#pragma unroll
    for (int j = 0; j < 8; j++) {
        float2 r0 = unpack2(acc[0][j]), r1 = unpack2(acc[1][j]);
        float2 r2 = unpack2(acc[2][j]), r3 = unpack2(acc[3][j]);
        float4 v0 = make_float4(r0.x, r1.x, r2.x, r3.x);
        float4 v1 = make_float4(r0.y, r1.y, r2.y, r3.y);
        *reinterpret_cast<float4*>(pp + (size_t)(2 * j) * NH)     = v0;
        *reinterpret_cast<float4*>(pp + (size_t)(2 * j + 1) * NH) = v1;
    }
}

// ---------------------------------------------------------------------------
// Kernel 3: out = part[0] + part[1]
// ---------------------------------------------------------------------------
__global__ __launch_bounds__(256) void moe_reduce_kernel(float* __restrict__ out)
{
    const size_t i = (size_t)blockIdx.x * 256 + threadIdx.x;   // float4 index
    const size_t n4 = (size_t)NE * NM * NH / 4;
    if (i < n4) {
        const float4* p0 = reinterpret_cast<const float4*>(g_part);
        const float4* p1 = reinterpret_cast<const float4*>(g_part + (size_t)NE * NM * NH);
        float4 a = p0[i], b = p1[i];
        float4 r = make_float4(a.x + b.x, a.y + b.y, a.z + b.z, a.w + b.w);
        reinterpret_cast<float4*>(out)[i] = r;
    }
}

extern "C" void kernel_launch(void* const* d_in, const int* in_sizes, int n_in,
                              void* d_out, int out_size)
{
    const float* x    = (const float*)d_in[0];  // [T=1024, H=2048]
    const float* gate = (const float*)d_in[1];  // [E, H, F]
    const float* up   = (const float*)d_in[2];  // [E, H, F]
    const float* down = (const float*)d_in[3];  // [E, F, H]
    float* out = (float*)d_out;                 // [T, H] fp32

    dim3 g1(NF / 128, NE);        // 11 x 64 = 704 CTAs, 64 thr
    moe_gateup_kernel<<<g1, 64>>>(x, gate, up);

    dim3 g2(NH / 256, NE, 2);     // 8 x 64 x 2 = 1024 CTAs, 64 thr
    moe_down_kernel<<<g2, 64>>>(down);

    const int n4 = NE * NM * NH / 4;              // 524288
    moe_reduce_kernel<<<(n4 + 255) / 256, 256>>>(out);
}

// round 17
// speedup vs baseline: 1.8344x; 1.8344x over previous
#include <cuda_runtime.h>

#define NE 64
#define NH 2048
#define NF 1408
#define NM 16

typedef unsigned long long ull;

// SwiGLU intermediate scratch: [E, M, F] fp32 = 5.77 MB
__device__ float g_inter[(size_t)NE * NM * NF];
// gate/up partial sums: [half(2) x mat(2)][E, M, F] fp32 = 23 MB
__device__ float g_pgu[(size_t)4 * NE * NM * NF];
// down-proj partial sums: [2, E, M, H] fp32 = 16.8 MB
__device__ float g_part[(size_t)2 * NE * NM * NH];

__device__ __forceinline__ ull pack2(float lo, float hi) {
    ull r;
    asm("mov.b64 %0, {%1, %2};" : "=l"(r) : "f"(lo), "f"(hi));
    return r;
}
__device__ __forceinline__ void fma2(ull& d, ull a, ull b) {
    asm("fma.rn.f32x2 %0, %1, %2, %0;" : "+l"(d) : "l"(a), "l"(b));
}
__device__ __forceinline__ float2 unpack2(ull v) {
    float2 r;
    asm("mov.b64 {%0, %1}, %2;" : "=f"(r.x), "=f"(r.y) : "l"(v));
    return r;
}
#define PF_L2(p) asm volatile("prefetch.global.L2 [%0];" :: "l"(p))

#define XS_PAD 20   // 80B row stride, 16B-aligned for LDS.128

// ---------------------------------------------------------------------------
// Kernel 1: partial gate/up accumulation over half of H.
// 64 thr/CTA, 2 f-cols/thread, depth-4 double-buffered weight prefetch
// + L2 software prefetch 16 h-steps ahead.  grid (11, 64, 2).
// ---------------------------------------------------------------------------
#define K1_HSPLIT 1024
#define K1_CHUNK 256
#define K1_NB (K1_CHUNK / 4)    // 64 blocks of 4 h-steps
#define K1_NP (K1_NB / 2)       // 32 pairs

__global__ __launch_bounds__(64) void moe_gateup_kernel(
    const float* __restrict__ x,
    const float* __restrict__ gate,
    const float* __restrict__ up)
{
    __shared__ float xs[K1_CHUNK][XS_PAD];

    const int e = blockIdx.y;
    const int z = blockIdx.z;
    const int tid = threadIdx.x;
    const int f = blockIdx.x * 128 + tid * 2;

    const float* xe = x + (size_t)e * NM * NH + (size_t)z * K1_HSPLIT;
    const float* gp = gate + (size_t)e * NH * NF + (size_t)z * K1_HSPLIT * NF + f;
    const float* upp = up + (size_t)e * NH * NF + (size_t)z * K1_HSPLIT * NF + f;
    // block-base pointers (no per-thread f offset) for L2 prefetch
    const float* gB = gate + (size_t)e * NH * NF + (size_t)z * K1_HSPLIT * NF + blockIdx.x * 128;
    const float* uB = up + (size_t)e * NH * NF + (size_t)z * K1_HSPLIT * NF + blockIdx.x * 128;
    // this thread's prefetch target: matrix = (tid&4)?up:gate, row offset tid>>3, line tid&3
    const float* pfbase = ((tid & 4) ? uB : gB) + (tid & 3) * 32;
    const int pfrow = tid >> 3;

    ull accg[2][8], accu[2][8];
#pragma unroll
    for (int c = 0; c < 2; c++)
#pragma unroll
        for (int j = 0; j < 8; j++) { accg[c][j] = 0ull; accu[c][j] = 0ull; }

    for (int hc = 0; hc < K1_HSPLIT; hc += K1_CHUNK) {
        __syncthreads();
#pragma unroll
        for (int mm = 0; mm < NM; mm++) {
#pragma unroll
            for (int hh = tid; hh < K1_CHUNK; hh += 64)
                xs[hh][mm] = xe[(size_t)mm * NH + hc + hh];
        }
        __syncthreads();

        const float* g0 = gp + (size_t)hc * NF;
        const float* u0 = upp + (size_t)hc * NF;

        float2 gA[4], uA[4], gB2[4], uB2[4];
#pragma unroll
        for (int s = 0; s < 4; s++) {
            gA[s] = __ldg((const float2*)(g0 + (size_t)s * NF));
            uA[s] = __ldg((const float2*)(u0 + (size_t)s * NF));
        }

        for (int p = 0; p < K1_NP; p++) {
            // L2 prefetch: h-steps 8p+16 .. 8p+23 (two pair-iterations ahead)
            {
                int hpf = hc + 8 * p + 16 + pfrow;
                if (hpf > K1_HSPLIT - 1) hpf = K1_HSPLIT - 1;
                PF_L2(pfbase + (size_t)hpf * NF);
            }
            const int b1 = 2 * p + 1;
            const int b2 = (2 * p + 2 < K1_NB) ? 2 * p + 2 : K1_NB - 1;
#pragma unroll
            for (int s = 0; s < 4; s++) {
                gB2[s] = __ldg((const float2*)(g0 + (size_t)(b1 * 4 + s) * NF));
                uB2[s] = __ldg((const float2*)(u0 + (size_t)(b1 * 4 + s) * NF));
            }
            {
                const int hb = 2 * p * 4;
#pragma unroll
                for (int s = 0; s < 4; s++) {
                    ull bg0 = pack2(gA[s].x, gA[s].x), bg1 = pack2(gA[s].y, gA[s].y);
                    ull bu0 = pack2(uA[s].x, uA[s].x), bu1 = pack2(uA[s].y, uA[s].y);
                    const ulonglong2* xr = reinterpret_cast<const ulonglong2*>(&xs[hb + s][0]);
                    ulonglong2 x01 = xr[0], x23 = xr[1], x45 = xr[2], x67 = xr[3];
                    fma2(accg[0][0], x01.x, bg0); fma2(accg[1][0], x01.x, bg1);
                    fma2(accu[0][0], x01.x, bu0); fma2(accu[1][0], x01.x, bu1);
                    fma2(accg[0][1], x01.y, bg0); fma2(accg[1][1], x01.y, bg1);
                    fma2(accu[0][1], x01.y, bu0); fma2(accu[1][1], x01.y, bu1);
                    fma2(accg[0][2], x23.x, bg0); fma2(accg[1][2], x23.x, bg1);
                    fma2(accu[0][2], x23.x, bu0); fma2(accu[1][2], x23.x, bu1);
                    fma2(accg[0][3], x23.y, bg0); fma2(accg[1][3], x23.y, bg1);
                    fma2(accu[0][3], x23.y, bu0); fma2(accu[1][3], x23.y, bu1);
                    fma2(accg[0][4], x45.x, bg0); fma2(accg[1][4], x45.x, bg1);
                    fma2(accu[0][4], x45.x, bu0); fma2(accu[1][4], x45.x, bu1);
                    fma2(accg[0][5], x45.y, bg0); fma2(accg[1][5], x45.y, bg1);
                    fma2(accu[0][5], x45.y, bu0); fma2(accu[1][5], x45.y, bu1);
                    fma2(accg[0][6], x67.x, bg0); fma2(accg[1][6], x67.x, bg1);
                    fma2(accu[0][6], x67.x, bu0); fma2(accu[1][6], x67.x, bu1);
                    fma2(accg[0][7], x67.y, bg0); fma2(accg[1][7], x67.y, bg1);
                    fma2(accu[0][7], x67.y, bu0); fma2(accu[1][7], x67.y, bu1);
                }
            }
#pragma unroll
            for (int s = 0; s < 4; s++) {
                gA[s] = __ldg((const float2*)(g0 + (size_t)(b2 * 4 + s) * NF));
                uA[s] = __ldg((const float2*)(u0 + (size_t)(b2 * 4 + s) * NF));
            }
            {
                const int hb = b1 * 4;
#pragma unroll
                for (int s = 0; s < 4; s++) {
                    ull bg0 = pack2(gB2[s].x, gB2[s].x), bg1 = pack2(gB2[s].y, gB2[s].y);
                    ull bu0 = pack2(uB2[s].x, uB2[s].x), bu1 = pack2(uB2[s].y, uB2[s].y);
                    const ulonglong2* xr = reinterpret_cast<const ulonglong2*>(&xs[hb + s][0]);
                    ulonglong2 x01 = xr[0], x23 = xr[1], x45 = xr[2], x67 = xr[3];
                    fma2(accg[0][0], x01.x, bg0); fma2(accg[1][0], x01.x, bg1);
                    fma2(accu[0][0], x01.x, bu0); fma2(accu[1][0], x01.x, bu1);
                    fma2(accg[0][1], x01.y, bg0); fma2(accg[1][1], x01.y, bg1);
                    fma2(accu[0][1], x01.y, bu0); fma2(accu[1][1], x01.y, bu1);
                    fma2(accg[0][2], x23.x, bg0); fma2(accg[1][2], x23.x, bg1);
                    fma2(accu[0][2], x23.x, bu0); fma2(accu[1][2], x23.x, bu1);
                    fma2(accg[0][3], x23.y, bg0); fma2(accg[1][3], x23.y, bg1);
                    fma2(accu[0][3], x23.y, bu0); fma2(accu[1][3], x23.y, bu1);
                    fma2(accg[0][4], x45.x, bg0); fma2(accg[1][4], x45.x, bg1);
                    fma2(accu[0][4], x45.x, bu0); fma2(accu[1][4], x45.x, bu1);
                    fma2(accg[0][5], x45.y, bg0); fma2(accg[1][5], x45.y, bg1);
                    fma2(accu[0][5], x45.y, bu0); fma2(accu[1][5], x45.y, bu1);
                    fma2(accg[0][6], x67.x, bg0); fma2(accg[1][6], x67.x, bg1);
                    fma2(accu[0][6], x67.x, bu0); fma2(accu[1][6], x67.x, bu1);
                    fma2(accg[0][7], x67.y, bg0); fma2(accg[1][7], x67.y, bg1);
                    fma2(accu[0][7], x67.y, bu0); fma2(accu[1][7], x67.y, bu1);
                }
            }
        }
    }

    // write partials: slot (z*2 + 0) = gate, (z*2 + 1) = up
    const size_t S = (size_t)NE * NM * NF;
    float* pg = g_pgu + (size_t)(z * 2 + 0) * S + (size_t)e * NM * NF + f;
    float* pu = g_pgu + (size_t)(z * 2 + 1) * S + (size_t)e * NM * NF + f;
#pragma unroll
    for (int j = 0; j < 8; j++) {
        float2 g0v = unpack2(accg[0][j]), g1v = unpack2(accg[1][j]);
        float2 u0v = unpack2(accu[0][j]), u1v = unpack2(accu[1][j]);
        float2 gm0 = make_float2(g0v.x, g1v.x);
        float2 gm1 = make_float2(g0v.y, g1v.y);
        float2 um0 = make_float2(u0v.x, u1v.x);
        float2 um1 = make_float2(u0v.y, u1v.y);
        *reinterpret_cast<float2*>(pg + (size_t)(2 * j) * NF)     = gm0;
        *reinterpret_cast<float2*>(pg + (size_t)(2 * j + 1) * NF) = gm1;
        *reinterpret_cast<float2*>(pu + (size_t)(2 * j) * NF)     = um0;
        *reinterpret_cast<float2*>(pu + (size_t)(2 * j + 1) * NF) = um1;
    }
}

// ---------------------------------------------------------------------------
// Kernel 1b: inter = silu(g0+g1) * (u0+u1)
// ---------------------------------------------------------------------------
__global__ __launch_bounds__(256) void moe_silu_kernel()
{
    const size_t S = (size_t)NE * NM * NF;
    const size_t n4 = S / 4;
    const size_t i = (size_t)blockIdx.x * 256 + threadIdx.x;
    if (i < n4) {
        const float4* G0 = reinterpret_cast<const float4*>(g_pgu + 0 * S);
        const float4* U0 = reinterpret_cast<const float4*>(g_pgu + 1 * S);
        const float4* G1 = reinterpret_cast<const float4*>(g_pgu + 2 * S);
        const float4* U1 = reinterpret_cast<const float4*>(g_pgu + 3 * S);
        float4 ga = G0[i], gb = G1[i], ua = U0[i], ub = U1[i];
        float gx = ga.x + gb.x, gy = ga.y + gb.y, gz = ga.z + gb.z, gw = ga.w + gb.w;
        float ux = ua.x + ub.x, uy = ua.y + ub.y, uz = ua.z + ub.z, uw = ua.w + ub.w;
        float4 r;
        r.x = gx / (1.0f + __expf(-gx)) * ux;
        r.y = gy / (1.0f + __expf(-gy)) * uy;
        r.z = gz / (1.0f + __expf(-gz)) * uz;
        r.w = gw / (1.0f + __expf(-gw)) * uw;
        reinterpret_cast<float4*>(g_inter)[i] = r;
    }
}

// ---------------------------------------------------------------------------
// Kernel 2: partial down-proj.  64 thr/CTA, 4 h-cols/thread, F-split 2,
// depth-4 double-buffered LDG.128 prefetch + L2 software prefetch
// 16 f-steps ahead.  grid (8, 64, 2).
// ---------------------------------------------------------------------------
#define K2_CHUNK 352
#define K2_FSPLIT 704
#define K2_NB (K2_CHUNK / 4)    // 88
#define K2_NP (K2_NB / 2)       // 44

__global__ __launch_bounds__(64) void moe_down_kernel(
    const float* __restrict__ down)
{
    __shared__ float xs[K2_CHUNK][XS_PAD];

    const int e = blockIdx.y;
    const int z = blockIdx.z;
    const int tid = threadIdx.x;
    const int h0 = blockIdx.x * 256 + tid * 4;

    const float* ie = g_inter + (size_t)e * NM * NF + (size_t)z * K2_FSPLIT;
    const float* dp = down + (size_t)e * NF * NH + (size_t)z * K2_FSPLIT * NH + h0;
    // prefetch base: row tid>>3 (8 rows), line tid&7 (8 x 128B = 1KB row)
    const float* dB = down + (size_t)e * NF * NH + (size_t)z * K2_FSPLIT * NH
                    + blockIdx.x * 256 + (tid & 7) * 32;
    const int pfrow = tid >> 3;

    ull acc[4][8];
#pragma unroll
    for (int c = 0; c < 4; c++)
#pragma unroll
        for (int j = 0; j < 8; j++) acc[c][j] = 0ull;

    for (int fc = 0; fc < K2_FSPLIT; fc += K2_CHUNK) {
        __syncthreads();
#pragma unroll
        for (int mm = 0; mm < NM; mm++) {
            for (int hh = tid; hh < K2_CHUNK; hh += 64)
                xs[hh][mm] = ie[(size_t)mm * NF + fc + hh];
        }
        __syncthreads();

        const float* d0 = dp + (size_t)fc * NH;

        float4 wA[4], wB[4];
#pragma unroll
        for (int s = 0; s < 4; s++)
            wA[s] = __ldg((const float4*)(d0 + (size_t)s * NH));

        for (int p = 0; p < K2_NP; p++) {
            // L2 prefetch: f-steps 8p+16 .. 8p+23 ahead
            {
                int fpf = fc + 8 * p + 16 + pfrow;
                if (fpf > K2_FSPLIT - 1) fpf = K2_FSPLIT - 1;
                PF_L2(dB + (size_t)fpf * NH);
            }
            const int b1 = 2 * p + 1;
            const int b2 = (2 * p + 2 < K2_NB) ? 2 * p + 2 : K2_NB - 1;
#pragma unroll
            for (int s = 0; s < 4; s++)
                wB[s] = __ldg((const float4*)(d0 + (size_t)(b1 * 4 + s) * NH));
            {
                const int hb = 2 * p * 4;
#pragma unroll
                for (int s = 0; s < 4; s++) {
                    ull b0 = pack2(wA[s].x, wA[s].x), b1w = pack2(wA[s].y, wA[s].y);
                    ull b2w = pack2(wA[s].z, wA[s].z), b3 = pack2(wA[s].w, wA[s].w);
                    const ulonglong2* xr = reinterpret_cast<const ulonglong2*>(&xs[hb + s][0]);
                    ulonglong2 x01 = xr[0], x23 = xr[1], x45 = xr[2], x67 = xr[3];
                    fma2(acc[0][0], x01.x, b0);  fma2(acc[1][0], x01.x, b1w);
                    fma2(acc[2][0], x01.x, b2w); fma2(acc[3][0], x01.x, b3);
                    fma2(acc[0][1], x01.y, b0);  fma2(acc[1][1], x01.y, b1w);
                    fma2(acc[2][1], x01.y, b2w); fma2(acc[3][1], x01.y, b3);
                    fma2(acc[0][2], x23.x, b0);  fma2(acc[1][2], x23.x, b1w);
                    fma2(acc[2][2], x23.x, b2w); fma2(acc[3][2], x23.x, b3);
                    fma2(acc[0][3], x23.y, b0);  fma2(acc[1][3], x23.y, b1w);
                    fma2(acc[2][3], x23.y, b2w); fma2(acc[3][3], x23.y, b3);
                    fma2(acc[0][4], x45.x, b0);  fma2(acc[1][4], x45.x, b1w);
                    fma2(acc[2][4], x45.x, b2w); fma2(acc[3][4], x45.x, b3);
                    fma2(acc[0][5], x45.y, b0);  fma2(acc[1][5], x45.y, b1w);
                    fma2(acc[2][5], x45.y, b2w); fma2(acc[3][5], x45.y, b3);
                    fma2(acc[0][6], x67.x, b0);  fma2(acc[1][6], x67.x, b1w);
                    fma2(acc[2][6], x67.x, b2w); fma2(acc[3][6], x67.x, b3);
                    fma2(acc[0][7], x67.y, b0);  fma2(acc[1][7], x67.y, b1w);
                    fma2(acc[2][7], x67.y, b2w); fma2(acc[3][7], x67.y, b3);
                }
            }
#pragma unroll
            for (int s = 0; s < 4; s++)
                wA[s] = __ldg((const float4*)(d0 + (size_t)(b2 * 4 + s) * NH));
            {
                const int hb = b1 * 4;
#pragma unroll
                for (int s = 0; s < 4; s++) {
                    ull b0 = pack2(wB[s].x, wB[s].x), b1w = pack2(wB[s].y, wB[s].y);
                    ull b2w = pack2(wB[s].z, wB[s].z), b3 = pack2(wB[s].w, wB[s].w);
                    const ulonglong2* xr = reinterpret_cast<const ulonglong2*>(&xs[hb + s][0]);
                    ulonglong2 x01 = xr[0], x23 = xr[1], x45 = xr[2], x67 = xr[3];
                    fma2(acc[0][0], x01.x, b0);  fma2(acc[1][0], x01.x, b1w);
                    fma2(acc[2][0], x01.x, b2w); fma2(acc[3][0], x01.x, b3);
                    fma2(acc[0][1], x01.y, b0);  fma2(acc[1][1], x01.y, b1w);
                    fma2(acc[2][1], x01.y, b2w); fma2(acc[3][1], x01.y, b3);
                    fma2(acc[0][2], x23.x, b0);  fma2(acc[1][2], x23.x, b1w);
                    fma2(acc[2][2], x23.x, b2w); fma2(acc[3][2], x23.x, b3);
                    fma2(acc[0][3], x23.y, b0);  fma2(acc[1][3], x23.y, b1w);
                    fma2(acc[2][3], x23.y, b2w); fma2(acc[3][3], x23.y, b3);
                    fma2(acc[0][4], x45.x, b0);  fma2(acc[1][4], x45.x, b1w);
                    fma2(acc[2][4], x45.x, b2w); fma2(acc[3][4], x45.x, b3);
                    fma2(acc[0][5], x45.y, b0);  fma2(acc[1][5], x45.y, b1w);
                    fma2(acc[2][5], x45.y, b2w); fma2(acc[3][5], x45.y, b3);
                    fma2(acc[0][6], x67.x, b0);  fma2(acc[1][6], x67.x, b1w);
                    fma2(acc[2][6], x67.x, b2w); fma2(acc[3][6], x67.x, b3);
                    fma2(acc[0][7], x67.y, b0);  fma2(acc[1][7], x67.y, b1w);
                    fma2(acc[2][7], x67.y, b2w); fma2(acc[3][7], x67.y, b3);
                }
            }
        }
    }

    float* pp = g_part + ((size_t)z * NE * NM + (size_t)e * NM) * NH + h0;
#pragma unroll
    for (int j = 0; j < 8; j++) {
        float2 r0 = unpack2(acc[0][j]), r1 = unpack2(acc[1][j]);
        float2 r2 = unpack2(acc[2][j]), r3 = unpack2(acc[3][j]);
        float4 v0 = make_float4(r0.x, r1.x, r2.x, r3.x);
        float4 v1 = make_float4(r0.y, r1.y, r2.y, r3.y);
        *reinterpret_cast<float4*>(pp + (size_t)(2 * j) * NH)     = v0;
        *reinterpret_cast<float4*>(pp + (size_t)(2 * j + 1) * NH) = v1;
    }
}

// ---------------------------------------------------------------------------
// Kernel 3: out = part[0] + part[1]
// ---------------------------------------------------------------------------
__global__ __launch_bounds__(256) void moe_reduce_kernel(float* __restrict__ out)
{
    const size_t i = (size_t)blockIdx.x * 256 + threadIdx.x;   // float4 index
    const size_t n4 = (size_t)NE * NM * NH / 4;
    if (i < n4) {
        const float4* p0 = reinterpret_cast<const float4*>(g_part);
        const float4* p1 = reinterpret_cast<const float4*>(g_part + (size_t)NE * NM * NH);
        float4 a = p0[i], b = p1[i];
        float4 r = make_float4(a.x + b.x, a.y + b.y, a.z + b.z, a.w + b.w);
        reinterpret_cast<float4*>(out)[i] = r;
    }
}

extern "C" void kernel_launch(void* const* d_in, const int* in_sizes, int n_in,
                              void* d_out, int out_size)
{
    const float* x    = (const float*)d_in[0];  // [T=1024, H=2048]
    const float* gate = (const float*)d_in[1];  // [E, H, F]
    const float* up   = (const float*)d_in[2];  // [E, H, F]
    const float* down = (const float*)d_in[3];  // [E, F, H]
    float* out = (float*)d_out;                 // [T, H] fp32

    dim3 g1(NF / 128, NE, 2);     // 11 x 64 x 2 = 1408 CTAs, 64 thr
    moe_gateup_kernel<<<g1, 64>>>(x, gate, up);

    const int nS4 = NE * NM * NF / 4;             // 360448
    moe_silu_kernel<<<(nS4 + 255) / 256, 256>>>();

    dim3 g2(NH / 256, NE, 2);     // 8 x 64 x 2 = 1024 CTAs, 64 thr
    moe_down_kernel<<<g2, 64>>>(down);

    const int n4 = NE * NM * NH / 4;              // 524288
    moe_reduce_kernel<<<(n4 + 255) / 256, 256>>>(out);
}